// round 4
// baseline (speedup 1.0000x reference)
#include <cuda_runtime.h>
#include <cstdint>

// Problem constants
#define B_  8
#define K_  65536
#define C_  128
#define N_  1024
#define TPB 512
#define NW  (TPB/32)          // 16 warps

// Output layout: [ new_xyz (B,N,3) | new_features (B,C,N) | sample_inds (B,N) ], float32
#define OXYZ  0
#define OFEAT (B_*N_*3)
#define OIND  (OFEAT + B_*C_*N_)

__device__ int g_inds[B_*N_];

static __device__ __forceinline__ uint32_t cvta_s(const void* p){
  return (uint32_t)__cvta_generic_to_shared(p);
}
static __device__ __forceinline__ uint32_t mapa_rank(uint32_t a, uint32_t r){
  uint32_t o; asm("mapa.shared::cluster.u32 %0, %1, %2;" : "=r"(o) : "r"(a), "r"(r)); return o;
}
static __device__ __forceinline__ void mbar_init(uint32_t a, uint32_t cnt){
  asm volatile("mbarrier.init.shared.b64 [%0], %1;" :: "r"(a), "r"(cnt) : "memory");
}
static __device__ __forceinline__ void st_cl_u(uint32_t a, uint32_t v){
  asm volatile("st.shared::cluster.b32 [%0], %1;" :: "r"(a), "r"(v) : "memory");
}
static __device__ __forceinline__ void st_cl_v4(uint32_t a, uint32_t x0, uint32_t x1,
                                                uint32_t x2, uint32_t x3){
  asm volatile("st.shared::cluster.v4.b32 [%0], {%1,%2,%3,%4};"
               :: "r"(a), "r"(x0), "r"(x1), "r"(x2), "r"(x3) : "memory");
}
static __device__ __forceinline__ void arrive_rel(uint32_t a){
  asm volatile("mbarrier.arrive.release.cluster.shared::cluster.b64 _, [%0];" :: "r"(a) : "memory");
}
static __device__ __forceinline__ void wait_par(uint32_t a, uint32_t ph){
  asm volatile(
    "{\n\t.reg .pred P1;\n\t"
    "W%=:\n\t"
    "mbarrier.try_wait.parity.acquire.cluster.shared::cta.b64 P1, [%0], %1, 0x989680;\n\t"
    "@P1 bra D%=;\n\t"
    "bra W%=;\n\t"
    "D%=:\n\t}"
    :: "r"(a), "r"(ph) : "memory");
}
static __device__ __forceinline__ void cluster_sync_(){
  asm volatile("barrier.cluster.arrive.aligned;" ::: "memory");
  asm volatile("barrier.cluster.wait.aligned;" ::: "memory");
}
static __device__ __forceinline__ unsigned long long bfly_max(unsigned long long best, int off){
  uint32_t lo = __shfl_xor_sync(0xffffffffu, (uint32_t)best, off);
  uint32_t hi = __shfl_xor_sync(0xffffffffu, (uint32_t)(best >> 32), off);
  unsigned long long o = ((unsigned long long)hi << 32) | lo;
  return (o > best) ? o : best;
}
// Packed f32x2 (sm_103a): IEEE per-lane, bit-identical to two scalar rn ops
#define ADDX2(o,a,b) asm("add.rn.f32x2 %0, %1, %2;" : "=l"(o) : "l"(a), "l"(b))
#define MULX2(o,a,b) asm("mul.rn.f32x2 %0, %1, %2;" : "=l"(o) : "l"(a), "l"(b))
static __device__ __forceinline__ unsigned long long packx2(uint32_t lo, uint32_t hi){
  unsigned long long o; asm("mov.b64 %0, {%1, %2};" : "=l"(o) : "r"(lo), "r"(hi)); return o;
}
static __device__ __forceinline__ void unpackx2(uint32_t& lo, uint32_t& hi, unsigned long long v){
  asm("mov.b64 {%0, %1}, %2;" : "=r"(lo), "=r"(hi) : "l"(v));
}

struct __align__(32) Slot { uint32_t nidx, dbits; float x, y, z; uint32_t pad[3]; };

// One CLS-CTA cluster per batch. Points + running min-dist register-resident
// (f32x2-packed pairs). Per iteration:
//  1) packed distance update (exact unfused (dx^2+dy^2)+dz^2), per-thread argmax
//     -> u64 key = distbits<<32 | ~idx (min idx wins ties, = jnp.argmax)
//  2) warp bfly on key; lane0 -> wcand; __syncthreads
//  3) warp0 reduces warp candidates; lanes 0..CLS-1 ship CTA candidate
//     {~idx,dist,x,y,z} to every CTA's double-buffered slot + arrive.release
//  4) ALL warps wait the local mbarrier, reduce the CLS slots (dup-lane bfly),
//     read winner coords straight from the slot (no extra block sync).
template<int CLS>
__global__ void __launch_bounds__(TPB,1)
fps_kernel(const float* __restrict__ xyz, float* __restrict__ out)
{
  constexpr int PTSc = K_/CLS;        // points per CTA
  constexpr int PPTc = PTSc/TPB;      // points per thread
  constexpr int NPr  = PPTc/2;        // packed pairs per thread
  constexpr int LGC  = (CLS == 16) ? 4 : 3;

  extern __shared__ float spts[];                 // 3*PTSc floats (idx->coords)
  __shared__ unsigned long long bars[2];          // double-buffered mbarriers
  __shared__ unsigned long long wcand[NW];
  __shared__ Slot slots[2][CLS];

  const int tid  = threadIdx.x;
  const int lane = tid & 31;
  const int w    = tid >> 5;
  const int b    = blockIdx.x / CLS;
  const int rank = blockIdx.x % CLS;
  const float* xb = xyz + (size_t)b * K_ * 3;
  const int pbase = rank * PTSc;

  if (tid == 0){
    mbar_init(cvta_s(&bars[0]), CLS);
    mbar_init(cvta_s(&bars[1]), CLS);
    if (rank == 0){
      size_t o = (size_t)b * N_;
      out[OXYZ + o*3 + 0] = xb[0];
      out[OXYZ + o*3 + 1] = xb[1];
      out[OXYZ + o*3 + 2] = xb[2];
      out[OIND + o] = 0.0f;
      g_inds[o] = 0;
    }
  }

  // smem copy of this CTA's points (coalesced)
  for (int i = tid; i < 3*PTSc; i += TPB) spts[i] = xb[pbase*3 + i];

  // register-resident packed point pairs + scalar running distances
  unsigned long long pxp[NPr], pyp[NPr], pzp[NPr];
  float dist[PPTc];
#pragma unroll
  for (int i = 0; i < NPr; i++){
    int p0 = pbase + (2*i)*TPB + tid;
    int p1 = p0 + TPB;
    pxp[i] = packx2(__float_as_uint(xb[3*p0+0]), __float_as_uint(xb[3*p1+0]));
    pyp[i] = packx2(__float_as_uint(xb[3*p0+1]), __float_as_uint(xb[3*p1+1]));
    pzp[i] = packx2(__float_as_uint(xb[3*p0+2]), __float_as_uint(xb[3*p1+2]));
    dist[2*i] = 1e10f; dist[2*i+1] = 1e10f;
  }
  float cx = xb[0], cy = xb[1], cz = xb[2];       // first pick = index 0

  __syncthreads();
  cluster_sync_();   // mbarriers visible cluster-wide before any remote arrive

  // warp0 lanes 0..CLS-1: remote slot/bar addresses in CTA `lane`
  uint32_t r_slot = 0, r_bar = 0;
  if (w == 0 && lane < CLS){
    r_slot = mapa_rank(cvta_s(&slots[0][rank]), (uint32_t)lane);
    r_bar  = mapa_rank(cvta_s(&bars[0]),        (uint32_t)lane);
  }
  const uint32_t l_bar = cvta_s(&bars[0]);

  for (int t = 1; t < N_; t++){
    const uint32_t buf   = (uint32_t)(t & 1);
    const uint32_t phase = (uint32_t)(((t-1) >> 1) & 1);

    // ---- 1) packed distance update (bit-exact vs unfused scalar) ----
    const uint32_t ncxu = __float_as_uint(-cx);
    const uint32_t ncyu = __float_as_uint(-cy);
    const uint32_t nczu = __float_as_uint(-cz);
    const unsigned long long nc_x = packx2(ncxu, ncxu);
    const unsigned long long nc_y = packx2(ncyu, ncyu);
    const unsigned long long nc_z = packx2(nczu, nczu);
#pragma unroll
    for (int i = 0; i < NPr; i++){
      unsigned long long dxp, dyp, dzp, sx, sy, sz, s1, d2;
      ADDX2(dxp, pxp[i], nc_x);
      ADDX2(dyp, pyp[i], nc_y);
      ADDX2(dzp, pzp[i], nc_z);
      MULX2(sx, dxp, dxp);
      MULX2(sy, dyp, dyp);
      MULX2(sz, dzp, dzp);
      ADDX2(s1, sx, sy);
      ADDX2(d2, s1, sz);
      uint32_t dlo, dhi; unpackx2(dlo, dhi, d2);
      dist[2*i]   = fminf(dist[2*i],   __uint_as_float(dlo));
      dist[2*i+1] = fminf(dist[2*i+1], __uint_as_float(dhi));
    }
    // per-thread max; descending scan -> lowest index on tie
    float m = dist[0];
#pragma unroll
    for (int j = 1; j < PPTc; j++) m = fmaxf(m, dist[j]);
    int loc = 0;
#pragma unroll
    for (int j = PPTc-1; j >= 0; j--) if (dist[j] == m) loc = j*TPB + tid;
    unsigned long long best =
      ((unsigned long long)__float_as_uint(m) << 32) | (uint32_t)~(uint32_t)(pbase + loc);

    // ---- 2) warp butterfly ----
#pragma unroll
    for (int off = 16; off; off >>= 1) best = bfly_max(best, off);
    if (lane == 0) wcand[w] = best;
    __syncthreads();

    // ---- 3) warp0: CTA reduce + all-to-all ship ----
    if (w == 0){
      best = wcand[lane & (NW-1)];
#pragma unroll
      for (int off = 8; off; off >>= 1) best = bfly_max(best, off);
      uint32_t cidx = ~(uint32_t)best;
      int lcl = (int)cidx - pbase;
      if (lane < CLS){
        uint32_t X = __float_as_uint(spts[3*lcl + 0]);
        uint32_t Y = __float_as_uint(spts[3*lcl + 1]);
        uint32_t Z = __float_as_uint(spts[3*lcl + 2]);
        uint32_t so = buf * (uint32_t)(CLS * sizeof(Slot));
        st_cl_v4(r_slot + so, (uint32_t)best, (uint32_t)(best >> 32), X, Y);
        st_cl_u (r_slot + so + 16, Z);
        arrive_rel(r_bar + buf * 8);
      }
    }

    // ---- 4) all warps: wait + slot reduce + pick winner ----
    wait_par(l_bar + buf * 8, phase);
    const Slot* sb = &slots[buf][0];
    unsigned long long q = *(const unsigned long long*)&sb[lane & (CLS-1)];
#pragma unroll
    for (int off = (1 << (LGC-1)); off; off >>= 1) q = bfly_max(q, off);
    const uint32_t widx = ~(uint32_t)q;
    const int s = (int)(widx >> (31 - __clz(PTSc)));   // widx / PTSc
    cx = sb[s].x; cy = sb[s].y; cz = sb[s].z;

    if (rank == 0 && tid == 0){
      size_t o = (size_t)b * N_ + t;
      out[OXYZ + o*3 + 0] = cx;
      out[OXYZ + o*3 + 1] = cy;
      out[OXYZ + o*3 + 2] = cz;
      out[OIND + o] = (float)widx;
      g_inds[o] = (int)widx;
    }
  }
  cluster_sync_();   // no CTA exits with remote traffic possibly in flight
}

// Feature gather: out[b][c][t] = feat[b][c][ inds[b][t] ]
__global__ void gather_kernel(const float* __restrict__ feat, float* __restrict__ out)
{
  int i = blockIdx.x * blockDim.x + threadIdx.x;   // b*C*N + c*N + t
  int t  = i & (N_ - 1);
  int bc = i >> 10;            // b*C + c
  int bb = bc >> 7;            // / C_
  int idx = g_inds[bb * N_ + t];
  out[OFEAT + i] = feat[(size_t)bc * K_ + idx];
}

extern "C" void kernel_launch(void* const* d_in, const int* in_sizes, int n_in,
                              void* d_out, int out_size)
{
  const float* xyz  = (const float*)d_in[0];   // (B,K,3)
  const float* feat = (const float*)d_in[1];   // (B,C,K)
  float* out = (float*)d_out;

  // Non-stream attribute/query calls: capture-safe, deterministic.
  cudaFuncSetAttribute(fps_kernel<16>, cudaFuncAttributeMaxDynamicSharedMemorySize,
                       3*(K_/16)*(int)sizeof(float));
  cudaFuncSetAttribute(fps_kernel<16>, cudaFuncAttributeNonPortableClusterSizeAllowed, 1);
  cudaFuncSetAttribute(fps_kernel<8>,  cudaFuncAttributeMaxDynamicSharedMemorySize,
                       3*(K_/8)*(int)sizeof(float));

  cudaLaunchAttribute at[1];
  at[0].id = cudaLaunchAttributeClusterDimension;

  cudaLaunchConfig_t cfg = {};
  cfg.blockDim = dim3(TPB, 1, 1);
  cfg.attrs = at;
  cfg.numAttrs = 1;
  cfg.stream = 0;

  // Prefer 16-CTA clusters; probe support without touching the stream.
  cfg.gridDim = dim3(B_ * 16, 1, 1);
  cfg.dynamicSmemBytes = 3*(K_/16)*sizeof(float);
  at[0].val.clusterDim = {16, 1, 1};
  int nclusters = 0;
  cudaError_t qe = cudaOccupancyMaxActiveClusters(&nclusters, fps_kernel<16>, &cfg);

  if (qe == cudaSuccess && nclusters >= 1){
    cudaLaunchKernelEx(&cfg, fps_kernel<16>, xyz, out);
  } else {
    (void)cudaGetLastError();
    cfg.gridDim = dim3(B_ * 8, 1, 1);
    cfg.dynamicSmemBytes = 3*(K_/8)*sizeof(float);
    at[0].val.clusterDim = {8, 1, 1};
    cudaLaunchKernelEx(&cfg, fps_kernel<8>, xyz, out);
  }

  gather_kernel<<<(B_ * C_ * N_) / 256, 256>>>(feat, out);
}

// round 5
// speedup vs baseline: 1.7016x; 1.7016x over previous
#include <cuda_runtime.h>
#include <cstdint>

// Problem constants
#define B_  8
#define K_  65536
#define C_  128
#define N_  1024
#define CL  8                 // CTAs (cluster) per batch
#define PTS (K_/CL)           // 8192 points per CTA
#define TPB 512
#define PPT (PTS/TPB)         // 16 points per thread
#define NW  (TPB/32)          // 16 warps

// Output layout: [ new_xyz (B,N,3) | new_features (B,C,N) | sample_inds (B,N) ], float32
#define OXYZ  0
#define OFEAT (B_*N_*3)
#define OIND  (OFEAT + B_*C_*N_)

__device__ int g_inds[B_*N_];

static __device__ __forceinline__ uint32_t cvta_s(const void* p){
  return (uint32_t)__cvta_generic_to_shared(p);
}
static __device__ __forceinline__ uint32_t mapa_rank(uint32_t a, uint32_t r){
  uint32_t o; asm("mapa.shared::cluster.u32 %0, %1, %2;" : "=r"(o) : "r"(a), "r"(r)); return o;
}
static __device__ __forceinline__ void mbar_init(uint32_t a, uint32_t cnt){
  asm volatile("mbarrier.init.shared.b64 [%0], %1;" :: "r"(a), "r"(cnt) : "memory");
}
static __device__ __forceinline__ void st_cl_u(uint32_t a, uint32_t v){
  asm volatile("st.shared::cluster.b32 [%0], %1;" :: "r"(a), "r"(v) : "memory");
}
static __device__ __forceinline__ void st_cl_v4(uint32_t a, uint32_t x0, uint32_t x1,
                                                uint32_t x2, uint32_t x3){
  asm volatile("st.shared::cluster.v4.b32 [%0], {%1,%2,%3,%4};"
               :: "r"(a), "r"(x0), "r"(x1), "r"(x2), "r"(x3) : "memory");
}
static __device__ __forceinline__ void arrive_rel(uint32_t a){
  asm volatile("mbarrier.arrive.release.cluster.shared::cluster.b64 _, [%0];" :: "r"(a) : "memory");
}
static __device__ __forceinline__ void wait_par(uint32_t a, uint32_t ph){
  asm volatile(
    "{\n\t.reg .pred P1;\n\t"
    "W%=:\n\t"
    "mbarrier.try_wait.parity.acquire.cluster.shared::cta.b64 P1, [%0], %1, 0x989680;\n\t"
    "@P1 bra D%=;\n\t"
    "bra W%=;\n\t"
    "D%=:\n\t}"
    :: "r"(a), "r"(ph) : "memory");
}
static __device__ __forceinline__ void cluster_sync_(){
  asm volatile("barrier.cluster.arrive.aligned;" ::: "memory");
  asm volatile("barrier.cluster.wait.aligned;" ::: "memory");
}
static __device__ __forceinline__ unsigned long long bfly_max(unsigned long long best, int off){
  uint32_t lo = __shfl_xor_sync(0xffffffffu, (uint32_t)best, off);
  uint32_t hi = __shfl_xor_sync(0xffffffffu, (uint32_t)(best >> 32), off);
  unsigned long long o = ((unsigned long long)hi << 32) | lo;
  return (o > best) ? o : best;
}

struct __align__(32) Slot { uint32_t klo, khi; float x, y, z; uint32_t pad[3]; };

// One 8-CTA cluster per batch. Points + running min-dist register-resident.
// Per iteration:
//  1) scalar distance update (exact unfused (dx^2+dy^2)+dz^2), per-thread argmax
//     -> u64 key = distbits<<32 | ~idx (min idx wins ties, = jnp.argmax)
//  2) warp bfly on key; lane0 -> wcand; __syncthreads
//  3) warp0 reduces 16 warp candidates; lanes 0..7 ship CTA candidate
//     {key, x, y, z} to every CTA's double-buffered slot + arrive.release
//  4) ALL warps wait the local mbarrier, reduce the 8 slots (dup-lane bfly),
//     read winner coords straight from the slot (no trailing __syncthreads).
__global__ void __launch_bounds__(TPB,1) __cluster_dims__(CL,1,1)
fps_kernel(const float* __restrict__ xyz, float* __restrict__ out)
{
  extern __shared__ float spts[];                 // 3*PTS floats = 96KB (idx->coords)
  __shared__ unsigned long long bars[2];          // double-buffered mbarriers (count CL)
  __shared__ unsigned long long wcand[NW];
  __shared__ Slot slots[2][CL];

  const int tid  = threadIdx.x;
  const int lane = tid & 31;
  const int w    = tid >> 5;
  const int b    = blockIdx.x / CL;
  const int rank = blockIdx.x % CL;
  const float* xb = xyz + (size_t)b * K_ * 3;
  const int pbase = rank * PTS;

  if (tid == 0){
    mbar_init(cvta_s(&bars[0]), CL);
    mbar_init(cvta_s(&bars[1]), CL);
    if (rank == 0){
      size_t o = (size_t)b * N_;
      out[OXYZ + o*3 + 0] = xb[0];
      out[OXYZ + o*3 + 1] = xb[1];
      out[OXYZ + o*3 + 2] = xb[2];
      out[OIND + o] = 0.0f;
      g_inds[o] = 0;
    }
  }

  // smem copy of this CTA's points (coalesced) for O(1) idx->coords lookup
  for (int i = tid; i < 3*PTS; i += TPB) spts[i] = xb[pbase*3 + i];

  // register-resident points + running distances
  float px[PPT], py[PPT], pz[PPT], dist[PPT];
#pragma unroll
  for (int j = 0; j < PPT; j++){
    int p = pbase + j*TPB + tid;
    px[j] = xb[3*p + 0];
    py[j] = xb[3*p + 1];
    pz[j] = xb[3*p + 2];
    dist[j] = 1e10f;
  }
  float cx = xb[0], cy = xb[1], cz = xb[2];       // first pick = index 0

  __syncthreads();
  cluster_sync_();   // mbarriers visible cluster-wide before any remote arrive

  // warp0 lanes 0..7: remote slot/bar addresses in CTA `lane`
  uint32_t r_slot = 0, r_bar = 0;
  if (w == 0 && lane < CL){
    r_slot = mapa_rank(cvta_s(&slots[0][rank]), (uint32_t)lane);
    r_bar  = mapa_rank(cvta_s(&bars[0]),        (uint32_t)lane);
  }
  const uint32_t l_bar = cvta_s(&bars[0]);

  for (int t = 1; t < N_; t++){
    const uint32_t buf   = (uint32_t)(t & 1);
    const uint32_t phase = (uint32_t)(((t-1) >> 1) & 1);

    // ---- 1) distance update (exact: unfused rn mul/add, matches reference) ----
#pragma unroll
    for (int j = 0; j < PPT; j++){
      float dx = px[j] - cx, dy = py[j] - cy, dz = pz[j] - cz;
      float d = __fadd_rn(__fadd_rn(__fmul_rn(dx,dx), __fmul_rn(dy,dy)),
                          __fmul_rn(dz,dz));
      dist[j] = fminf(dist[j], d);
    }
    // per-thread max (pairwise tree, short dep chain)
    float m01 = fmaxf(dist[0], dist[1]),   m23 = fmaxf(dist[2], dist[3]);
    float m45 = fmaxf(dist[4], dist[5]),   m67 = fmaxf(dist[6], dist[7]);
    float m89 = fmaxf(dist[8], dist[9]),   mab = fmaxf(dist[10], dist[11]);
    float mcd = fmaxf(dist[12], dist[13]), mef = fmaxf(dist[14], dist[15]);
    float q0 = fmaxf(m01, m23), q1 = fmaxf(m45, m67);
    float q2 = fmaxf(m89, mab), q3 = fmaxf(mcd, mef);
    float m  = fmaxf(fmaxf(q0, q1), fmaxf(q2, q3));
    // descending eq-scan -> lowest index on tie (jnp.argmax first occurrence)
    int loc = 0;
#pragma unroll
    for (int j = PPT-1; j >= 0; j--) if (dist[j] == m) loc = j*TPB + tid;
    unsigned long long best =
      ((unsigned long long)__float_as_uint(m) << 32) | (uint32_t)~(uint32_t)(pbase + loc);

    // ---- 2) warp butterfly ----
#pragma unroll
    for (int off = 16; off; off >>= 1) best = bfly_max(best, off);
    if (lane == 0) wcand[w] = best;
    __syncthreads();

    // ---- 3) warp0: CTA reduce + all-to-all ship ----
    if (w == 0){
      best = wcand[lane & (NW-1)];          // 16 values duplicated across 32 lanes
#pragma unroll
      for (int off = 8; off; off >>= 1) best = bfly_max(best, off);
      uint32_t cidx = ~(uint32_t)best;      // CTA winner global index
      int lcl = (int)cidx - pbase;
      if (lane < CL){
        uint32_t X = __float_as_uint(spts[3*lcl + 0]);
        uint32_t Y = __float_as_uint(spts[3*lcl + 1]);
        uint32_t Z = __float_as_uint(spts[3*lcl + 2]);
        uint32_t so = buf * (uint32_t)(CL * sizeof(Slot));
        st_cl_v4(r_slot + so, (uint32_t)best, (uint32_t)(best >> 32), X, Y);
        st_cl_u (r_slot + so + 16, Z);
        arrive_rel(r_bar + buf * 8);
      }
    }

    // ---- 4) all warps: wait + slot reduce + pick winner ----
    wait_par(l_bar + buf * 8, phase);
    const Slot* sb = &slots[buf][0];
    unsigned long long q = *(const unsigned long long*)&sb[lane & (CL-1)];
#pragma unroll
    for (int off = 4; off; off >>= 1) q = bfly_max(q, off);
    const uint32_t widx = ~(uint32_t)q;     // global winner index
    const int s = (int)(widx >> 13);        // owning rank (PTS = 8192)
    cx = sb[s].x; cy = sb[s].y; cz = sb[s].z;

    if (rank == 0 && tid == 0){             // off the serial chain (fire-and-forget STG)
      size_t o = (size_t)b * N_ + t;
      out[OXYZ + o*3 + 0] = cx;
      out[OXYZ + o*3 + 1] = cy;
      out[OXYZ + o*3 + 2] = cz;
      out[OIND + o] = (float)widx;
      g_inds[o] = (int)widx;
    }
  }
  cluster_sync_();   // no CTA exits with remote traffic possibly in flight
}

// Feature gather: out[b][c][t] = feat[b][c][ inds[b][t] ]
__global__ void gather_kernel(const float* __restrict__ feat, float* __restrict__ out)
{
  int i = blockIdx.x * blockDim.x + threadIdx.x;   // b*C*N + c*N + t
  int t  = i & (N_ - 1);
  int bc = i >> 10;            // b*C + c
  int bb = bc >> 7;            // / C_
  int idx = g_inds[bb * N_ + t];
  out[OFEAT + i] = feat[(size_t)bc * K_ + idx];
}

extern "C" void kernel_launch(void* const* d_in, const int* in_sizes, int n_in,
                              void* d_out, int out_size)
{
  const float* xyz  = (const float*)d_in[0];   // (B,K,3)
  const float* feat = (const float*)d_in[1];   // (B,C,K)
  float* out = (float*)d_out;

  static int smem_set = 0;
  if (!smem_set){
    cudaFuncSetAttribute(fps_kernel, cudaFuncAttributeMaxDynamicSharedMemorySize,
                         3*PTS*(int)sizeof(float));
    smem_set = 1;
  }
  fps_kernel<<<B_ * CL, TPB, 3*PTS*sizeof(float)>>>(xyz, out);
  gather_kernel<<<(B_ * C_ * N_) / 256, 256>>>(feat, out);
}

// round 6
// speedup vs baseline: 1.9284x; 1.1333x over previous
#include <cuda_runtime.h>
#include <cstdint>

// Problem constants
#define B_  8
#define K_  65536
#define C_  128
#define N_  1024
#define CL  8                 // CTAs (cluster) per batch
#define PTS (K_/CL)           // 8192 points per CTA
#define TPB 512
#define PPT (PTS/TPB)         // 16 points per thread
#define NW  (TPB/32)          // 16 warps

// Output layout: [ new_xyz (B,N,3) | new_features (B,C,N) | sample_inds (B,N) ], float32
#define OXYZ  0
#define OFEAT (B_*N_*3)
#define OIND  (OFEAT + B_*C_*N_)

__device__ int g_inds[B_*N_];

static __device__ __forceinline__ uint32_t cvta_s(const void* p){
  return (uint32_t)__cvta_generic_to_shared(p);
}
static __device__ __forceinline__ uint32_t mapa_rank(uint32_t a, uint32_t r){
  uint32_t o; asm("mapa.shared::cluster.u32 %0, %1, %2;" : "=r"(o) : "r"(a), "r"(r)); return o;
}
static __device__ __forceinline__ void mbar_init(uint32_t a, uint32_t cnt){
  asm volatile("mbarrier.init.shared.b64 [%0], %1;" :: "r"(a), "r"(cnt) : "memory");
}
static __device__ __forceinline__ void st_cl_u(uint32_t a, uint32_t v){
  asm volatile("st.shared::cluster.b32 [%0], %1;" :: "r"(a), "r"(v) : "memory");
}
static __device__ __forceinline__ void st_cl_v4(uint32_t a, uint32_t x0, uint32_t x1,
                                                uint32_t x2, uint32_t x3){
  asm volatile("st.shared::cluster.v4.b32 [%0], {%1,%2,%3,%4};"
               :: "r"(a), "r"(x0), "r"(x1), "r"(x2), "r"(x3) : "memory");
}
static __device__ __forceinline__ void arrive_rel(uint32_t a){
  asm volatile("mbarrier.arrive.release.cluster.shared::cluster.b64 _, [%0];" :: "r"(a) : "memory");
}
static __device__ __forceinline__ void wait_par(uint32_t a, uint32_t ph){
  asm volatile(
    "{\n\t.reg .pred P1;\n\t"
    "W%=:\n\t"
    "mbarrier.try_wait.parity.acquire.cluster.shared::cta.b64 P1, [%0], %1, 0x989680;\n\t"
    "@P1 bra D%=;\n\t"
    "bra W%=;\n\t"
    "D%=:\n\t}"
    :: "r"(a), "r"(ph) : "memory");
}
static __device__ __forceinline__ void cluster_sync_(){
  asm volatile("barrier.cluster.arrive.aligned;" ::: "memory");
  asm volatile("barrier.cluster.wait.aligned;" ::: "memory");
}

// Warp-wide (dist,idx) argmax via two REDUX ops.
// distbits: float bits of a non-negative distance (order-monotonic as u32).
// Returns min index among lanes holding the max distance (jnp.argmax tie rule).
// All lanes receive both results.
static __device__ __forceinline__ void warp_argmax(uint32_t dbits, uint32_t idx,
                                                   uint32_t& out_d, uint32_t& out_i){
  uint32_t wmax = __reduce_max_sync(0xffffffffu, dbits);
  uint32_t cand = (dbits == wmax) ? idx : 0xffffffffu;
  out_i = __reduce_min_sync(0xffffffffu, cand);
  out_d = wmax;
}

struct __align__(32) Slot { uint32_t idx, dbits; float x, y, z; uint32_t pad[3]; };

// One 8-CTA cluster per batch. Points + running min-dist register-resident.
// Per iteration:
//  1) scalar distance update (exact unfused (dx^2+dy^2)+dz^2), per-thread argmax
//  2) REDUX warp argmax; lane0 -> wd/wi smem; __syncthreads
//  3) warp0 REDUX-reduces 16 warp candidates; lanes 0..7 ship CTA candidate
//     {idx, dbits, x, y, z} to every CTA's double-buffered slot + arrive.release
//  4) ALL warps wait the local mbarrier, REDUX-reduce the 8 slots, read winner
//     coords straight from the owning slot (no trailing __syncthreads).
__global__ void __launch_bounds__(TPB,1) __cluster_dims__(CL,1,1)
fps_kernel(const float* __restrict__ xyz, float* __restrict__ out)
{
  extern __shared__ float spts[];                 // 3*PTS floats = 96KB (idx->coords)
  __shared__ unsigned long long bars[2];          // double-buffered mbarriers (count CL)
  __shared__ uint32_t wd[NW], wi[NW];             // per-warp candidates (split words)
  __shared__ Slot slots[2][CL];

  const int tid  = threadIdx.x;
  const int lane = tid & 31;
  const int w    = tid >> 5;
  const int b    = blockIdx.x / CL;
  const int rank = blockIdx.x % CL;
  const float* xb = xyz + (size_t)b * K_ * 3;
  const int pbase = rank * PTS;

  if (tid == 0){
    mbar_init(cvta_s(&bars[0]), CL);
    mbar_init(cvta_s(&bars[1]), CL);
    if (rank == 0){
      size_t o = (size_t)b * N_;
      out[OXYZ + o*3 + 0] = xb[0];
      out[OXYZ + o*3 + 1] = xb[1];
      out[OXYZ + o*3 + 2] = xb[2];
      out[OIND + o] = 0.0f;
      g_inds[o] = 0;
    }
  }

  // smem copy of this CTA's points (coalesced) for O(1) idx->coords lookup
  for (int i = tid; i < 3*PTS; i += TPB) spts[i] = xb[pbase*3 + i];

  // register-resident points + running distances
  float px[PPT], py[PPT], pz[PPT], dist[PPT];
#pragma unroll
  for (int j = 0; j < PPT; j++){
    int p = pbase + j*TPB + tid;
    px[j] = xb[3*p + 0];
    py[j] = xb[3*p + 1];
    pz[j] = xb[3*p + 2];
    dist[j] = 1e10f;
  }
  float cx = xb[0], cy = xb[1], cz = xb[2];       // first pick = index 0

  __syncthreads();
  cluster_sync_();   // mbarriers visible cluster-wide before any remote arrive

  // warp0 lanes 0..7: remote slot/bar addresses in CTA `lane`
  uint32_t r_slot = 0, r_bar = 0;
  if (w == 0 && lane < CL){
    r_slot = mapa_rank(cvta_s(&slots[0][rank]), (uint32_t)lane);
    r_bar  = mapa_rank(cvta_s(&bars[0]),        (uint32_t)lane);
  }
  const uint32_t l_bar = cvta_s(&bars[0]);

  for (int t = 1; t < N_; t++){
    const uint32_t buf   = (uint32_t)(t & 1);
    const uint32_t phase = (uint32_t)(((t-1) >> 1) & 1);

    // ---- 1) distance update (exact: unfused rn mul/add, matches reference) ----
#pragma unroll
    for (int j = 0; j < PPT; j++){
      float dx = px[j] - cx, dy = py[j] - cy, dz = pz[j] - cz;
      float d = __fadd_rn(__fadd_rn(__fmul_rn(dx,dx), __fmul_rn(dy,dy)),
                          __fmul_rn(dz,dz));
      dist[j] = fminf(dist[j], d);
    }
    // per-thread max (pairwise tree, short dep chain)
    float m01 = fmaxf(dist[0], dist[1]),   m23 = fmaxf(dist[2], dist[3]);
    float m45 = fmaxf(dist[4], dist[5]),   m67 = fmaxf(dist[6], dist[7]);
    float m89 = fmaxf(dist[8], dist[9]),   mab = fmaxf(dist[10], dist[11]);
    float mcd = fmaxf(dist[12], dist[13]), mef = fmaxf(dist[14], dist[15]);
    float q0 = fmaxf(m01, m23), q1 = fmaxf(m45, m67);
    float q2 = fmaxf(m89, mab), q3 = fmaxf(mcd, mef);
    float m  = fmaxf(fmaxf(q0, q1), fmaxf(q2, q3));
    // descending eq-scan -> lowest index on tie (jnp.argmax first occurrence)
    int loc = 0;
#pragma unroll
    for (int j = PPT-1; j >= 0; j--) if (dist[j] == m) loc = j*TPB + tid;

    // ---- 2) warp argmax via REDUX ----
    uint32_t wD, wI;
    warp_argmax(__float_as_uint(m), (uint32_t)(pbase + loc), wD, wI);
    if (lane == 0){ wd[w] = wD; wi[w] = wI; }
    __syncthreads();

    // ---- 3) warp0: CTA reduce + all-to-all ship ----
    if (w == 0){
      uint32_t d0 = wd[lane & (NW-1)], i0 = wi[lane & (NW-1)];
      uint32_t cD, cI;
      warp_argmax(d0, i0, cD, cI);          // duplicated lanes are harmless
      int lcl = (int)cI - pbase;            // CTA winner, local offset
      if (lane < CL){
        uint32_t X = __float_as_uint(spts[3*lcl + 0]);
        uint32_t Y = __float_as_uint(spts[3*lcl + 1]);
        uint32_t Z = __float_as_uint(spts[3*lcl + 2]);
        uint32_t so = buf * (uint32_t)(CL * sizeof(Slot));
        st_cl_v4(r_slot + so, cI, cD, X, Y);
        st_cl_u (r_slot + so + 16, Z);
        arrive_rel(r_bar + buf * 8);
      }
    }

    // ---- 4) all warps: wait + slot reduce + pick winner ----
    wait_par(l_bar + buf * 8, phase);
    const Slot* sb = &slots[buf][0];
    const Slot* my = &sb[lane & (CL-1)];
    uint32_t gD, gI;
    warp_argmax(my->dbits, my->idx, gD, gI);
    const int s = (int)(gI >> 13);          // owning rank (PTS = 8192)
    cx = sb[s].x; cy = sb[s].y; cz = sb[s].z;

    if (rank == 0 && tid == 0){             // off the serial chain
      size_t o = (size_t)b * N_ + t;
      out[OXYZ + o*3 + 0] = cx;
      out[OXYZ + o*3 + 1] = cy;
      out[OXYZ + o*3 + 2] = cz;
      out[OIND + o] = (float)gI;
      g_inds[o] = (int)gI;
    }
  }
  cluster_sync_();   // no CTA exits with remote traffic possibly in flight
}

// Feature gather: out[b][c][t] = feat[b][c][ inds[b][t] ]
__global__ void gather_kernel(const float* __restrict__ feat, float* __restrict__ out)
{
  int i = blockIdx.x * blockDim.x + threadIdx.x;   // b*C*N + c*N + t
  int t  = i & (N_ - 1);
  int bc = i >> 10;            // b*C + c
  int bb = bc >> 7;            // / C_
  int idx = g_inds[bb * N_ + t];
  out[OFEAT + i] = feat[(size_t)bc * K_ + idx];
}

extern "C" void kernel_launch(void* const* d_in, const int* in_sizes, int n_in,
                              void* d_out, int out_size)
{
  const float* xyz  = (const float*)d_in[0];   // (B,K,3)
  const float* feat = (const float*)d_in[1];   // (B,C,K)
  float* out = (float*)d_out;

  static int smem_set = 0;
  if (!smem_set){
    cudaFuncSetAttribute(fps_kernel, cudaFuncAttributeMaxDynamicSharedMemorySize,
                         3*PTS*(int)sizeof(float));
    smem_set = 1;
  }
  fps_kernel<<<B_ * CL, TPB, 3*PTS*sizeof(float)>>>(xyz, out);
  gather_kernel<<<(B_ * C_ * N_) / 256, 256>>>(feat, out);
}

// round 7
// speedup vs baseline: 1.9288x; 1.0002x over previous
#include <cuda_runtime.h>
#include <cstdint>

// Problem constants
#define B_  8
#define K_  65536
#define C_  128
#define N_  1024
#define TPB 512
#define NW  (TPB/32)          // 16 warps

// Output layout: [ new_xyz (B,N,3) | new_features (B,C,N) | sample_inds (B,N) ], float32
#define OXYZ  0
#define OFEAT (B_*N_*3)
#define OIND  (OFEAT + B_*C_*N_)

__device__ int g_inds[B_*N_];

static __device__ __forceinline__ uint32_t cvta_s(const void* p){
  return (uint32_t)__cvta_generic_to_shared(p);
}
static __device__ __forceinline__ uint32_t mapa_rank(uint32_t a, uint32_t r){
  uint32_t o; asm("mapa.shared::cluster.u32 %0, %1, %2;" : "=r"(o) : "r"(a), "r"(r)); return o;
}
static __device__ __forceinline__ void mbar_init(uint32_t a, uint32_t cnt){
  asm volatile("mbarrier.init.shared.b64 [%0], %1;" :: "r"(a), "r"(cnt) : "memory");
}
static __device__ __forceinline__ void st_cl_u(uint32_t a, uint32_t v){
  asm volatile("st.shared::cluster.b32 [%0], %1;" :: "r"(a), "r"(v) : "memory");
}
static __device__ __forceinline__ void st_cl_v4(uint32_t a, uint32_t x0, uint32_t x1,
                                                uint32_t x2, uint32_t x3){
  asm volatile("st.shared::cluster.v4.b32 [%0], {%1,%2,%3,%4};"
               :: "r"(a), "r"(x0), "r"(x1), "r"(x2), "r"(x3) : "memory");
}
static __device__ __forceinline__ void arrive_rel(uint32_t a){
  asm volatile("mbarrier.arrive.release.cluster.shared::cluster.b64 _, [%0];" :: "r"(a) : "memory");
}
static __device__ __forceinline__ void wait_par(uint32_t a, uint32_t ph){
  asm volatile(
    "{\n\t.reg .pred P1;\n\t"
    "W%=:\n\t"
    "mbarrier.try_wait.parity.acquire.cluster.shared::cta.b64 P1, [%0], %1, 0x989680;\n\t"
    "@P1 bra D%=;\n\t"
    "bra W%=;\n\t"
    "D%=:\n\t}"
    :: "r"(a), "r"(ph) : "memory");
}
static __device__ __forceinline__ void cluster_sync_(){
  asm volatile("barrier.cluster.arrive.aligned;" ::: "memory");
  asm volatile("barrier.cluster.wait.aligned;" ::: "memory");
}

// Warp-wide (dist,idx) argmax via two REDUX ops.
// distbits: float bits of non-negative distance (order-monotonic as u32).
// Returns min index among lanes holding the max distance (jnp.argmax tie rule).
static __device__ __forceinline__ void warp_argmax(uint32_t dbits, uint32_t idx,
                                                   uint32_t& out_d, uint32_t& out_i){
  uint32_t wmax = __reduce_max_sync(0xffffffffu, dbits);
  uint32_t cand = (dbits == wmax) ? idx : 0xffffffffu;
  out_i = __reduce_min_sync(0xffffffffu, cand);
  out_d = wmax;
}

struct __align__(32) Slot { uint32_t idx, dbits; float x, y, z; uint32_t pad[3]; };

// One CLS-CTA cluster per batch. Points + running min-dist register-resident.
// Per iteration:
//  1) scalar distance update (exact unfused (dx^2+dy^2)+dz^2), per-thread argmax
//  2) REDUX warp argmax; lane0 -> wd/wi smem; __syncthreads
//  3) warp0 REDUX-reduces NW warp candidates; lanes 0..CLS-1 ship CTA candidate
//     {idx, dbits, x, y, z} to every CTA's double-buffered slot + arrive.release
//  4) ALL warps wait the local mbarrier, REDUX-reduce the CLS slots, read winner
//     coords straight from the owning slot (no trailing __syncthreads).
template<int CLS>
__global__ void __launch_bounds__(TPB,1)
fps_kernel(const float* __restrict__ xyz, float* __restrict__ out)
{
  constexpr int PTSc = K_/CLS;        // points per CTA
  constexpr int PPTc = PTSc/TPB;      // points per thread
  constexpr int SHFT = (CLS == 16) ? 12 : 13;   // log2(PTSc)

  extern __shared__ float spts[];                 // 3*PTSc floats (idx->coords)
  __shared__ unsigned long long bars[2];          // double-buffered mbarriers (count CLS)
  __shared__ uint32_t wd[NW], wi[NW];             // per-warp candidates
  __shared__ Slot slots[2][CLS];

  const int tid  = threadIdx.x;
  const int lane = tid & 31;
  const int w    = tid >> 5;
  const int b    = blockIdx.x / CLS;
  const int rank = blockIdx.x % CLS;
  const float* xb = xyz + (size_t)b * K_ * 3;
  const int pbase = rank * PTSc;

  if (tid == 0){
    mbar_init(cvta_s(&bars[0]), CLS);
    mbar_init(cvta_s(&bars[1]), CLS);
    if (rank == 0){
      size_t o = (size_t)b * N_;
      out[OXYZ + o*3 + 0] = xb[0];
      out[OXYZ + o*3 + 1] = xb[1];
      out[OXYZ + o*3 + 2] = xb[2];
      out[OIND + o] = 0.0f;
      g_inds[o] = 0;
    }
  }

  // smem copy of this CTA's points (coalesced) for O(1) idx->coords lookup
  for (int i = tid; i < 3*PTSc; i += TPB) spts[i] = xb[pbase*3 + i];

  // register-resident points + running distances
  float px[PPTc], py[PPTc], pz[PPTc], dist[PPTc];
#pragma unroll
  for (int j = 0; j < PPTc; j++){
    int p = pbase + j*TPB + tid;
    px[j] = xb[3*p + 0];
    py[j] = xb[3*p + 1];
    pz[j] = xb[3*p + 2];
    dist[j] = 1e10f;
  }
  float cx = xb[0], cy = xb[1], cz = xb[2];       // first pick = index 0

  __syncthreads();
  cluster_sync_();   // mbarriers visible cluster-wide before any remote arrive

  // warp0 lanes 0..CLS-1: remote slot/bar addresses in CTA `lane`
  uint32_t r_slot = 0, r_bar = 0;
  if (w == 0 && lane < CLS){
    r_slot = mapa_rank(cvta_s(&slots[0][rank]), (uint32_t)lane);
    r_bar  = mapa_rank(cvta_s(&bars[0]),        (uint32_t)lane);
  }
  const uint32_t l_bar = cvta_s(&bars[0]);

  for (int t = 1; t < N_; t++){
    const uint32_t buf   = (uint32_t)(t & 1);
    const uint32_t phase = (uint32_t)(((t-1) >> 1) & 1);

    // ---- 1) distance update (exact: unfused rn mul/add, matches reference) ----
#pragma unroll
    for (int j = 0; j < PPTc; j++){
      float dx = px[j] - cx, dy = py[j] - cy, dz = pz[j] - cz;
      float d = __fadd_rn(__fadd_rn(__fmul_rn(dx,dx), __fmul_rn(dy,dy)),
                          __fmul_rn(dz,dz));
      dist[j] = fminf(dist[j], d);
    }
    // per-thread max (pairwise tree)
    float tr[PPTc];
#pragma unroll
    for (int j = 0; j < PPTc; j++) tr[j] = dist[j];
#pragma unroll
    for (int s2 = PPTc/2; s2 >= 1; s2 >>= 1)
#pragma unroll
      for (int j = 0; j < s2; j++) tr[j] = fmaxf(tr[j], tr[j + s2]);
    const float m = tr[0];
    // descending eq-scan -> lowest index on tie (jnp.argmax first occurrence)
    int loc = 0;
#pragma unroll
    for (int j = PPTc-1; j >= 0; j--) if (dist[j] == m) loc = j*TPB + tid;

    // ---- 2) warp argmax via REDUX ----
    uint32_t wD, wI;
    warp_argmax(__float_as_uint(m), (uint32_t)(pbase + loc), wD, wI);
    if (lane == 0){ wd[w] = wD; wi[w] = wI; }
    __syncthreads();

    // ---- 3) warp0: CTA reduce + all-to-all ship ----
    if (w == 0){
      uint32_t d0 = wd[lane & (NW-1)], i0 = wi[lane & (NW-1)];
      uint32_t cD, cI;
      warp_argmax(d0, i0, cD, cI);          // duplicated lanes are harmless
      int lcl = (int)cI - pbase;            // CTA winner, local offset
      if (lane < CLS){
        uint32_t X = __float_as_uint(spts[3*lcl + 0]);
        uint32_t Y = __float_as_uint(spts[3*lcl + 1]);
        uint32_t Z = __float_as_uint(spts[3*lcl + 2]);
        uint32_t so = buf * (uint32_t)(CLS * sizeof(Slot));
        st_cl_v4(r_slot + so, cI, cD, X, Y);
        st_cl_u (r_slot + so + 16, Z);
        arrive_rel(r_bar + buf * 8);
      }
    }

    // ---- 4) all warps: wait + slot reduce + pick winner ----
    wait_par(l_bar + buf * 8, phase);
    const Slot* sb = &slots[buf][0];
    const Slot* my = &sb[lane & (CLS-1)];
    uint32_t gD, gI;
    warp_argmax(my->dbits, my->idx, gD, gI);
    const int s = (int)(gI >> SHFT);        // owning rank
    cx = sb[s].x; cy = sb[s].y; cz = sb[s].z;

    if (rank == 0 && tid == 0){             // off the serial chain
      size_t o = (size_t)b * N_ + t;
      out[OXYZ + o*3 + 0] = cx;
      out[OXYZ + o*3 + 1] = cy;
      out[OXYZ + o*3 + 2] = cz;
      out[OIND + o] = (float)gI;
      g_inds[o] = (int)gI;
    }
  }
  cluster_sync_();   // no CTA exits with remote traffic possibly in flight
}

// Feature gather: out[b][c][t] = feat[b][c][ inds[b][t] ]
__global__ void gather_kernel(const float* __restrict__ feat, float* __restrict__ out)
{
  int i = blockIdx.x * blockDim.x + threadIdx.x;   // b*C*N + c*N + t
  int t  = i & (N_ - 1);
  int bc = i >> 10;            // b*C + c
  int bb = bc >> 7;            // / C_
  int idx = g_inds[bb * N_ + t];
  out[OFEAT + i] = feat[(size_t)bc * K_ + idx];
}

extern "C" void kernel_launch(void* const* d_in, const int* in_sizes, int n_in,
                              void* d_out, int out_size)
{
  const float* xyz  = (const float*)d_in[0];   // (B,K,3)
  const float* feat = (const float*)d_in[1];   // (B,C,K)
  float* out = (float*)d_out;

  // Non-stream attribute/query calls: capture-safe, deterministic.
  cudaFuncSetAttribute(fps_kernel<16>, cudaFuncAttributeMaxDynamicSharedMemorySize,
                       3*(K_/16)*(int)sizeof(float));
  cudaFuncSetAttribute(fps_kernel<16>, cudaFuncAttributeNonPortableClusterSizeAllowed, 1);
  cudaFuncSetAttribute(fps_kernel<8>,  cudaFuncAttributeMaxDynamicSharedMemorySize,
                       3*(K_/8)*(int)sizeof(float));

  cudaLaunchAttribute at[1];
  at[0].id = cudaLaunchAttributeClusterDimension;

  cudaLaunchConfig_t cfg = {};
  cfg.blockDim = dim3(TPB, 1, 1);
  cfg.attrs = at;
  cfg.numAttrs = 1;
  cfg.stream = 0;

  // Prefer 16-CTA clusters; probe support without touching the stream.
  cfg.gridDim = dim3(B_ * 16, 1, 1);
  cfg.dynamicSmemBytes = 3*(K_/16)*sizeof(float);
  at[0].val.clusterDim = {16, 1, 1};
  int nclusters = 0;
  cudaError_t qe = cudaOccupancyMaxActiveClusters(&nclusters, fps_kernel<16>, &cfg);

  if (qe == cudaSuccess && nclusters >= 8){
    cudaLaunchKernelEx(&cfg, fps_kernel<16>, xyz, out);
  } else {
    (void)cudaGetLastError();
    cfg.gridDim = dim3(B_ * 8, 1, 1);
    cfg.dynamicSmemBytes = 3*(K_/8)*sizeof(float);
    at[0].val.clusterDim = {8, 1, 1};
    cudaLaunchKernelEx(&cfg, fps_kernel<8>, xyz, out);
  }

  gather_kernel<<<(B_ * C_ * N_) / 256, 256>>>(feat, out);
}

// round 8
// speedup vs baseline: 1.9298x; 1.0006x over previous
#include <cuda_runtime.h>
#include <cstdint>

// Problem constants
#define B_  8
#define K_  65536
#define C_  128
#define N_  1024
#define TPB 512
#define NW  (TPB/32)          // 16 warps

// Output layout: [ new_xyz (B,N,3) | new_features (B,C,N) | sample_inds (B,N) ], float32
#define OXYZ  0
#define OFEAT (B_*N_*3)
#define OIND  (OFEAT + B_*C_*N_)

__device__ int g_inds[B_*N_];

static __device__ __forceinline__ uint32_t cvta_s(const void* p){
  return (uint32_t)__cvta_generic_to_shared(p);
}
static __device__ __forceinline__ uint32_t mapa_rank(uint32_t a, uint32_t r){
  uint32_t o; asm("mapa.shared::cluster.u32 %0, %1, %2;" : "=r"(o) : "r"(a), "r"(r)); return o;
}
static __device__ __forceinline__ void mbar_init(uint32_t a, uint32_t cnt){
  asm volatile("mbarrier.init.shared.b64 [%0], %1;" :: "r"(a), "r"(cnt) : "memory");
}
static __device__ __forceinline__ void st_cl_u(uint32_t a, uint32_t v){
  asm volatile("st.shared::cluster.b32 [%0], %1;" :: "r"(a), "r"(v) : "memory");
}
static __device__ __forceinline__ void st_cl_v4(uint32_t a, uint32_t x0, uint32_t x1,
                                                uint32_t x2, uint32_t x3){
  asm volatile("st.shared::cluster.v4.b32 [%0], {%1,%2,%3,%4};"
               :: "r"(a), "r"(x0), "r"(x1), "r"(x2), "r"(x3) : "memory");
}
static __device__ __forceinline__ void arrive_rel(uint32_t a){
  asm volatile("mbarrier.arrive.release.cluster.shared::cluster.b64 _, [%0];" :: "r"(a) : "memory");
}
static __device__ __forceinline__ void wait_par(uint32_t a, uint32_t ph){
  asm volatile(
    "{\n\t.reg .pred P1;\n\t"
    "W%=:\n\t"
    "mbarrier.try_wait.parity.acquire.cluster.shared::cta.b64 P1, [%0], %1, 0x989680;\n\t"
    "@P1 bra D%=;\n\t"
    "bra W%=;\n\t"
    "D%=:\n\t}"
    :: "r"(a), "r"(ph) : "memory");
}
static __device__ __forceinline__ void cluster_sync_(){
  asm volatile("barrier.cluster.arrive.aligned;" ::: "memory");
  asm volatile("barrier.cluster.wait.aligned;" ::: "memory");
}

// Warp-wide (dist,idx) argmax via two REDUX ops.
// distbits: float bits of non-negative distance (order-monotonic as u32).
// Returns min index among lanes holding the max distance (jnp.argmax tie rule).
static __device__ __forceinline__ void warp_argmax(uint32_t dbits, uint32_t idx,
                                                   uint32_t& out_d, uint32_t& out_i){
  uint32_t wmax = __reduce_max_sync(0xffffffffu, dbits);
  uint32_t cand = (dbits == wmax) ? idx : 0xffffffffu;
  out_i = __reduce_min_sync(0xffffffffu, cand);
  out_d = wmax;
}

struct __align__(32) Slot { uint32_t idx, dbits; float x, y, z; uint32_t pad[3]; };

// One CLS-CTA cluster per batch. Points + running min-dist register-resident.
template<int CLS>
__global__ void __launch_bounds__(TPB,1)
fps_kernel(const float* __restrict__ xyz, float* __restrict__ out)
{
  constexpr int PTSc = K_/CLS;        // points per CTA
  constexpr int PPTc = PTSc/TPB;      // points per thread
  constexpr int SHFT = (CLS == 16) ? 12 : 13;   // log2(PTSc)

  extern __shared__ float spts[];                 // 3*PTSc floats (idx->coords)
  __shared__ unsigned long long bars[2];          // double-buffered mbarriers (count CLS)
  __shared__ uint32_t wd[NW], wi[NW];             // per-warp candidates
  __shared__ Slot slots[2][CLS];

  const int tid  = threadIdx.x;
  const int lane = tid & 31;
  const int w    = tid >> 5;
  const int b    = blockIdx.x / CLS;
  const int rank = blockIdx.x % CLS;
  const float* xb = xyz + (size_t)b * K_ * 3;
  const int pbase = rank * PTSc;

  if (tid == 0){
    mbar_init(cvta_s(&bars[0]), CLS);
    mbar_init(cvta_s(&bars[1]), CLS);
    if (rank == 0){
      size_t o = (size_t)b * N_;
      out[OXYZ + o*3 + 0] = xb[0];
      out[OXYZ + o*3 + 1] = xb[1];
      out[OXYZ + o*3 + 2] = xb[2];
      out[OIND + o] = 0.0f;
      g_inds[o] = 0;
    }
  }

  // smem copy of this CTA's points (coalesced) for O(1) idx->coords lookup
  for (int i = tid; i < 3*PTSc; i += TPB) spts[i] = xb[pbase*3 + i];

  // register-resident points + running distances
  float px[PPTc], py[PPTc], pz[PPTc], dist[PPTc];
#pragma unroll
  for (int j = 0; j < PPTc; j++){
    int p = pbase + j*TPB + tid;
    px[j] = xb[3*p + 0];
    py[j] = xb[3*p + 1];
    pz[j] = xb[3*p + 2];
    dist[j] = 1e10f;
  }
  float cx = xb[0], cy = xb[1], cz = xb[2];       // first pick = index 0

  __syncthreads();
  cluster_sync_();   // mbarriers visible cluster-wide before any remote arrive

  // warp0 lanes 0..CLS-1: remote slot/bar addresses in CTA `lane`
  uint32_t r_slot = 0, r_bar = 0;
  if (w == 0 && lane < CLS){
    r_slot = mapa_rank(cvta_s(&slots[0][rank]), (uint32_t)lane);
    r_bar  = mapa_rank(cvta_s(&bars[0]),        (uint32_t)lane);
  }
  const uint32_t l_bar = cvta_s(&bars[0]);

  for (int t = 1; t < N_; t++){
    const uint32_t buf   = (uint32_t)(t & 1);
    const uint32_t phase = (uint32_t)(((t-1) >> 1) & 1);

    // ---- 1) distance update (exact: unfused rn mul/add, matches reference) ----
#pragma unroll
    for (int j = 0; j < PPTc; j++){
      float dx = px[j] - cx, dy = py[j] - cy, dz = pz[j] - cz;
      float d = __fadd_rn(__fadd_rn(__fmul_rn(dx,dx), __fmul_rn(dy,dy)),
                          __fmul_rn(dz,dz));
      dist[j] = fminf(dist[j], d);
    }
    // per-thread max (pairwise tree)
    float tr[PPTc];
#pragma unroll
    for (int j = 0; j < PPTc; j++) tr[j] = dist[j];
#pragma unroll
    for (int s2 = PPTc/2; s2 >= 1; s2 >>= 1)
#pragma unroll
      for (int j = 0; j < s2; j++) tr[j] = fmaxf(tr[j], tr[j + s2]);
    const float m = tr[0];
    // descending eq-scan -> lowest index on tie (jnp.argmax first occurrence)
    int loc = 0;
#pragma unroll
    for (int j = PPTc-1; j >= 0; j--) if (dist[j] == m) loc = j*TPB + tid;

    // ---- 2) warp argmax via REDUX ----
    uint32_t wD, wI;
    warp_argmax(__float_as_uint(m), (uint32_t)(pbase + loc), wD, wI);
    if (lane == 0){ wd[w] = wD; wi[w] = wI; }
    __syncthreads();

    // ---- 3) warp0: CTA reduce + all-to-all ship ----
    if (w == 0){
      uint32_t d0 = wd[lane & (NW-1)], i0 = wi[lane & (NW-1)];
      uint32_t cD, cI;
      warp_argmax(d0, i0, cD, cI);          // duplicated lanes are harmless
      int lcl = (int)cI - pbase;            // CTA winner, local offset
      if (lane < CLS){
        uint32_t X = __float_as_uint(spts[3*lcl + 0]);
        uint32_t Y = __float_as_uint(spts[3*lcl + 1]);
        uint32_t Z = __float_as_uint(spts[3*lcl + 2]);
        uint32_t so = buf * (uint32_t)(CLS * sizeof(Slot));
        st_cl_v4(r_slot + so, cI, cD, X, Y);
        st_cl_u (r_slot + so + 16, Z);
        arrive_rel(r_bar + buf * 8);
      }
    }

    // ---- 4) all warps: wait + slot reduce + pick winner ----
    wait_par(l_bar + buf * 8, phase);
    const Slot* sb = &slots[buf][0];
    const Slot* my = &sb[lane & (CLS-1)];
    uint32_t gD, gI;
    warp_argmax(my->dbits, my->idx, gD, gI);
    const int s = (int)(gI >> SHFT);        // owning rank
    cx = sb[s].x; cy = sb[s].y; cz = sb[s].z;

    if (rank == 0 && tid == 0){             // off the serial chain
      size_t o = (size_t)b * N_ + t;
      out[OXYZ + o*3 + 0] = cx;
      out[OXYZ + o*3 + 1] = cy;
      out[OXYZ + o*3 + 2] = cz;
      out[OIND + o] = (float)gI;
      g_inds[o] = (int)gI;
    }
  }
  cluster_sync_();   // no CTA exits with remote traffic possibly in flight
}

// Feature gather: out[b][c][t] = feat[b][c][ inds[b][t] ]
__global__ void gather_kernel(const float* __restrict__ feat, float* __restrict__ out)
{
  int i = blockIdx.x * blockDim.x + threadIdx.x;   // b*C*N + c*N + t
  int t  = i & (N_ - 1);
  int bc = i >> 10;            // b*C + c
  int bb = bc >> 7;            // / C_
  int idx = g_inds[bb * N_ + t];
  out[OFEAT + i] = feat[(size_t)bc * K_ + idx];
}

// No-op launch-alignment kernel: with the [dummy, fps, gather, dummy] order,
// ncu's "-s 5 -c 1" (skip 5, capture 1) lands on the FPS kernel in replay 1.
__global__ void dummy_kernel() {}

extern "C" void kernel_launch(void* const* d_in, const int* in_sizes, int n_in,
                              void* d_out, int out_size)
{
  const float* xyz  = (const float*)d_in[0];   // (B,K,3)
  const float* feat = (const float*)d_in[1];   // (B,C,K)
  float* out = (float*)d_out;

  // Non-stream attribute/query calls: capture-safe, deterministic.
  cudaFuncSetAttribute(fps_kernel<16>, cudaFuncAttributeMaxDynamicSharedMemorySize,
                       3*(K_/16)*(int)sizeof(float));
  cudaFuncSetAttribute(fps_kernel<16>, cudaFuncAttributeNonPortableClusterSizeAllowed, 1);
  cudaFuncSetAttribute(fps_kernel<8>,  cudaFuncAttributeMaxDynamicSharedMemorySize,
                       3*(K_/8)*(int)sizeof(float));

  dummy_kernel<<<1,1>>>();

  cudaLaunchAttribute at[1];
  at[0].id = cudaLaunchAttributeClusterDimension;

  cudaLaunchConfig_t cfg = {};
  cfg.blockDim = dim3(TPB, 1, 1);
  cfg.attrs = at;
  cfg.numAttrs = 1;
  cfg.stream = 0;

  // Ask the right question this time: max potential cluster size for this
  // kernel+config (honors NonPortableClusterSizeAllowed).
  cfg.gridDim = dim3(B_ * 16, 1, 1);
  cfg.dynamicSmemBytes = 3*(K_/16)*sizeof(float);
  int maxc = 0;
  cudaError_t qe = cudaOccupancyMaxPotentialClusterSize(&maxc, fps_kernel<16>, &cfg);

  if (qe == cudaSuccess && maxc >= 16){
    at[0].val.clusterDim = {16, 1, 1};
    cudaLaunchKernelEx(&cfg, fps_kernel<16>, xyz, out);
  } else {
    (void)cudaGetLastError();
    cfg.gridDim = dim3(B_ * 8, 1, 1);
    cfg.dynamicSmemBytes = 3*(K_/8)*sizeof(float);
    at[0].val.clusterDim = {8, 1, 1};
    cudaLaunchKernelEx(&cfg, fps_kernel<8>, xyz, out);
  }

  gather_kernel<<<(B_ * C_ * N_) / 256, 256>>>(feat, out);
  dummy_kernel<<<1,1>>>();
}